// round 13
// baseline (speedup 1.0000x reference)
#include <cuda_runtime.h>
#include <cuda_bf16.h>
#include <cstdint>
#include <cstddef>

// ---------------------------------------------------------------------------
// Packed fp32x2 FMA (Blackwell): two fp32 FMAs per issue slot.
// ---------------------------------------------------------------------------
#define FMA_F32X2(d, a, b) \
    asm("fma.rn.f32x2 %0, %1, %2, %0;" : "+l"(d) : "l"(a), "l"(b))

// ---------------------------------------------------------------------------
// Scratch (device globals) — identical to the R2-passing kernel.
//   g_out1 : layer1 output, [pix(256)][chan(64)][b(4096)] feature-major
//   g_out2 : layer2 output, [feat(3136)=o*49+p2][b]
//   g_h1   : fc1 output, [1024][b];  g_h2 : fc2 output, [512][b]
// ---------------------------------------------------------------------------
__device__ float g_out1[256 * 64 * 4096];
__device__ float g_out2[3136 * 4096];
__device__ float g_h1[1024 * 4096];
__device__ float g_h2[512 * 4096];

static constexpr int BATCH = 4096;

// ---------------------------------------------------------------------------
// Layer 1 (verbatim from R2-passing kernel)
// ---------------------------------------------------------------------------
__global__ __launch_bounds__(256) void layer1_kernel(
    const float* __restrict__ x, const float* __restrict__ w1)
{
    __shared__ float patch[64 * 13];
    __shared__ float wts[64 * 13];

    const int p     = blockIdx.x;
    const int bbase = blockIdx.y * 64;
    const int h     = p >> 4;
    const int wcol  = p & 15;
    const int t     = threadIdx.x;

    for (int idx = t; idx < 768; idx += 256) {
        int o = idx / 12, j = idx % 12;
        wts[o * 13 + j] = w1[(size_t)o * 3072 + p * 12 + j];
    }
    for (int idx = t; idx < 384; idx += 256) {
        int b = idx / 6, q = idx % 6;
        int c = q >> 1, kh = q & 1;
        const float* xb = x + ((size_t)(bbase + b) * 3 + c) * 1024
                            + (2 * h + kh) * 32 + 2 * wcol;
        float2 v = *reinterpret_cast<const float2*>(xb);
        patch[b * 13 + q * 2]     = v.x;
        patch[b * 13 + q * 2 + 1] = v.y;
    }
    __syncthreads();

    const int b0 = (t & 15) * 4;
    const int o0 = (t >> 4) * 4;
    float acc[4][4] = {};
#pragma unroll
    for (int j = 0; j < 12; j++) {
        float a[4], wv[4];
#pragma unroll
        for (int i = 0; i < 4; i++) {
            a[i]  = patch[(b0 + i) * 13 + j];
            wv[i] = wts[(o0 + i) * 13 + j];
        }
#pragma unroll
        for (int io = 0; io < 4; io++)
#pragma unroll
            for (int ib = 0; ib < 4; ib++)
                acc[io][ib] = fmaf(wv[io], a[ib], acc[io][ib]);
    }
#pragma unroll
    for (int io = 0; io < 4; io++) {
        float4 v;
        v.x = fmaxf(acc[io][0], 0.0f);
        v.y = fmaxf(acc[io][1], 0.0f);
        v.z = fmaxf(acc[io][2], 0.0f);
        v.w = fmaxf(acc[io][3], 0.0f);
        float* dst = g_out1 + (size_t)(p * 64 + o0 + io) * BATCH + bbase + b0;
        *reinterpret_cast<float4*>(dst) = v;
    }
}

// ---------------------------------------------------------------------------
// Feature-major f32x2 GEMM (R2 structure; NF selects o-frags per thread).
//   C[crow(o)][b] = act( sum_k A[arow(k)][b] * W[wrow(o)][k] )
// BM=128 (batch), BN=16*NF, BK=16.  NF=4: exact R2 config (layer2 gather).
// NF=8: BN=128, halves LDS-per-FLOP (for FC1/FC2).
// ---------------------------------------------------------------------------
template <int ABUF, int CBUF, bool GATHER, bool RELU, int NF>
__global__ __launch_bounds__(256, (NF == 4 ? 2 : 1)) void gemm_kernel(
    const float* __restrict__ W, int Kdim)
{
    constexpr int BM = 128, BK = 16, PAD = 18;
    constexpr int BN = 16 * NF;
    __shared__ __align__(16) float As[BM * PAD];  // [b_local][k]
    __shared__ __align__(16) float Ws[BN * PAD];  // [o_local][k]

    const float* A = (ABUF == 0) ? g_out1 : (ABUF == 1) ? g_out2
                   : (ABUF == 2) ? g_h1   : g_h2;
    float* C       = (CBUF == 1) ? g_out2 : (CBUF == 2) ? g_h1 : g_h2;

    const int t     = threadIdx.x;
    const int bbase = blockIdx.x * BM;
    const int obase = blockIdx.y * BN;
    const int p2    = GATHER ? (int)blockIdx.z : 0;
    const int h2    = p2 / 7;
    const int w2    = p2 % 7;

    // A-load mapping (identical to R2)
    const int ka  = t >> 4;          // k row 0..15
    const int ca  = (t & 15) * 4;    // batch offset

    // W-load mapping: NF==4 -> R2 exact; NF==8 -> 128 rows, 2 float4/thread
    const int owr4 = t >> 2, kw4 = (t & 3) * 4;      // NF==4
    const int owr8 = t >> 1, kw8 = (t & 1) * 8;      // NF==8

    float4 ra0, ra1, rw0, rw1;

    unsigned long long acc[8][NF];
#pragma unroll
    for (int i = 0; i < 8; i++)
#pragma unroll
        for (int j = 0; j < NF; j++) acc[i][j] = 0ull;

    const int tx = t & 15;   // batch sub-index
    const int ty = t >> 4;   // feature sub-index

    for (int k0 = 0; k0 < Kdim; k0 += BK) {
        // ---- global loads into regs ----
        {
            const int k = k0 + ka;
            const float* arow;
            if (GATHER) {
                int c = k >> 4, kh = (k >> 2) & 3, kw = k & 3;
                int pix = (2 * h2 + kh) * 16 + (2 * w2 + kw);
                arow = A + (size_t)(pix * 64 + c) * BATCH;
            } else {
                arow = A + (size_t)k * BATCH;
            }
            ra0 = *reinterpret_cast<const float4*>(arow + bbase + ca);
            ra1 = *reinterpret_cast<const float4*>(arow + bbase + ca + 64);
            if (NF == 4) {
                const float* wrow;
                if (GATHER) wrow = W + ((size_t)(obase + owr4) * 49 + p2) * 1024 + k0 + kw4;
                else        wrow = W + (size_t)(obase + owr4) * Kdim + k0 + kw4;
                rw0 = *reinterpret_cast<const float4*>(wrow);
            } else {
                const float* wrow = W + (size_t)(obase + owr8) * Kdim + k0 + kw8;
                rw0 = *reinterpret_cast<const float4*>(wrow);
                rw1 = *reinterpret_cast<const float4*>(wrow + 4);
            }
        }

        __syncthreads();
        // ---- commit to smem (transposed A) ----
        As[(ca + 0) * PAD + ka] = ra0.x;
        As[(ca + 1) * PAD + ka] = ra0.y;
        As[(ca + 2) * PAD + ka] = ra0.z;
        As[(ca + 3) * PAD + ka] = ra0.w;
        As[(ca + 64) * PAD + ka] = ra1.x;
        As[(ca + 65) * PAD + ka] = ra1.y;
        As[(ca + 66) * PAD + ka] = ra1.z;
        As[(ca + 67) * PAD + ka] = ra1.w;
        if (NF == 4) {
            Ws[owr4 * PAD + kw4 + 0] = rw0.x;
            Ws[owr4 * PAD + kw4 + 1] = rw0.y;
            Ws[owr4 * PAD + kw4 + 2] = rw0.z;
            Ws[owr4 * PAD + kw4 + 3] = rw0.w;
        } else {
            Ws[owr8 * PAD + kw8 + 0] = rw0.x;
            Ws[owr8 * PAD + kw8 + 1] = rw0.y;
            Ws[owr8 * PAD + kw8 + 2] = rw0.z;
            Ws[owr8 * PAD + kw8 + 3] = rw0.w;
            Ws[owr8 * PAD + kw8 + 4] = rw1.x;
            Ws[owr8 * PAD + kw8 + 5] = rw1.y;
            Ws[owr8 * PAD + kw8 + 6] = rw1.z;
            Ws[owr8 * PAD + kw8 + 7] = rw1.w;
        }
        __syncthreads();

        // ---- compute: K packed two-at-a-time into f32x2 lanes ----
#pragma unroll
        for (int kk = 0; kk < BK; kk += 2) {
            unsigned long long a2[8], w2r[NF];
#pragma unroll
            for (int i = 0; i < 8; i++)
                a2[i] = *reinterpret_cast<const unsigned long long*>(
                    &As[(tx + i * 16) * PAD + kk]);
#pragma unroll
            for (int j = 0; j < NF; j++)
                w2r[j] = *reinterpret_cast<const unsigned long long*>(
                    &Ws[(ty + j * 16) * PAD + kk]);
#pragma unroll
            for (int i = 0; i < 8; i++)
#pragma unroll
                for (int j = 0; j < NF; j++)
                    FMA_F32X2(acc[i][j], a2[i], w2r[j]);
        }
    }

    // ---- epilogue: fold K-lanes, activation, feature-major store ----
#pragma unroll
    for (int j = 0; j < NF; j++) {
        const int o = obase + ty + j * 16;
        const size_t crow = GATHER ? (size_t)(o * 49 + p2) : (size_t)o;
        float* cb = C + crow * BATCH + bbase + tx;
#pragma unroll
        for (int i = 0; i < 8; i++) {
            unsigned long long v = acc[i][j];
            float lo = __uint_as_float((unsigned)(v & 0xffffffffu));
            float hi = __uint_as_float((unsigned)(v >> 32));
            float r = lo + hi;
            if (RELU) r = fmaxf(r, 0.0f);
            cb[i * 16] = r;
        }
    }
}

// ---------------------------------------------------------------------------
// FC3 (verbatim from R2-passing kernel)
// ---------------------------------------------------------------------------
__global__ __launch_bounds__(256) void fc3_kernel(
    const float* __restrict__ W, float* __restrict__ out)
{
    __shared__ float Ws[10 * 512];
    for (int i = threadIdx.x; i < 5120; i += 256) Ws[i] = W[i];
    __syncthreads();

    const int b = blockIdx.x * 256 + threadIdx.x;
    float acc[10] = {};
    for (int k = 0; k < 512; k++) {
        float a = g_h2[(size_t)k * BATCH + b];
#pragma unroll
        for (int o = 0; o < 10; o++)
            acc[o] = fmaf(a, Ws[o * 512 + k], acc[o]);
    }
#pragma unroll
    for (int o = 0; o < 10; o++) out[(size_t)b * 10 + o] = acc[o];
}

// ---------------------------------------------------------------------------
// kernel_launch (same 5-launch structure as R2)
// ---------------------------------------------------------------------------
extern "C" void kernel_launch(void* const* d_in, const int* in_sizes, int n_in,
                              void* d_out, int out_size)
{
    (void)in_sizes; (void)n_in; (void)out_size;
    const float* x      = (const float*)d_in[0];
    const float* conv1w = (const float*)d_in[1];
    const float* conv2w = (const float*)d_in[2];
    const float* fc1    = (const float*)d_in[3];
    const float* fc2    = (const float*)d_in[4];
    const float* fc3    = (const float*)d_in[5];
    float* out          = (float*)d_out;

    // Layer 1: 256 positions x 64 batch tiles
    layer1_kernel<<<dim3(256, 64), 256>>>(x, conv1w);

    // Layer 2: 49 x (M=4096, N=64, K=1024) — exact R2 config (NF=4)
    gemm_kernel<0, 1, true, true, 4><<<dim3(32, 1, 49), 256>>>(conv2w, 1024);

    // FC1: M=4096, N=1024, K=3136 — NF=8 (BN=128)
    gemm_kernel<1, 2, false, true, 8><<<dim3(32, 8), 256>>>(fc1, 3136);

    // FC2: M=4096, N=512, K=1024 — NF=8 (BN=128)
    gemm_kernel<2, 3, false, true, 8><<<dim3(32, 4), 256>>>(fc2, 1024);

    // FC3: M=4096, N=10, K=512
    fc3_kernel<<<16, 256>>>(fc3, out);
}

// round 14
// speedup vs baseline: 1.1038x; 1.1038x over previous
#include <cuda_runtime.h>
#include <cuda_bf16.h>
#include <cstdint>
#include <cstddef>

// ---------------------------------------------------------------------------
// Packed fp32x2 FMA (Blackwell): two fp32 FMAs per issue slot.
// ---------------------------------------------------------------------------
#define FMA_F32X2(d, a, b) \
    asm("fma.rn.f32x2 %0, %1, %2, %0;" : "+l"(d) : "l"(a), "l"(b))

// ---------------------------------------------------------------------------
// Scratch (device globals) — identical to the R2-passing kernel.
//   g_out1 : layer1 output, [pix(256)][chan(64)][b(4096)] feature-major
//   g_out2 : layer2 output, [feat(3136)=o*49+p2][b]
//   g_h1   : fc1 output, [1024][b];  g_h2 : fc2 output, [512][b]
// ---------------------------------------------------------------------------
__device__ float g_out1[256 * 64 * 4096];
__device__ float g_out2[3136 * 4096];
__device__ float g_h1[1024 * 4096];
__device__ float g_h2[512 * 4096];

static constexpr int BATCH = 4096;

// ---------------------------------------------------------------------------
// Layer 1 (verbatim from R2-passing kernel)
// ---------------------------------------------------------------------------
__global__ __launch_bounds__(256) void layer1_kernel(
    const float* __restrict__ x, const float* __restrict__ w1)
{
    __shared__ float patch[64 * 13];
    __shared__ float wts[64 * 13];

    const int p     = blockIdx.x;
    const int bbase = blockIdx.y * 64;
    const int h     = p >> 4;
    const int wcol  = p & 15;
    const int t     = threadIdx.x;

    for (int idx = t; idx < 768; idx += 256) {
        int o = idx / 12, j = idx % 12;
        wts[o * 13 + j] = w1[(size_t)o * 3072 + p * 12 + j];
    }
    for (int idx = t; idx < 384; idx += 256) {
        int b = idx / 6, q = idx % 6;
        int c = q >> 1, kh = q & 1;
        const float* xb = x + ((size_t)(bbase + b) * 3 + c) * 1024
                            + (2 * h + kh) * 32 + 2 * wcol;
        float2 v = *reinterpret_cast<const float2*>(xb);
        patch[b * 13 + q * 2]     = v.x;
        patch[b * 13 + q * 2 + 1] = v.y;
    }
    __syncthreads();

    const int b0 = (t & 15) * 4;
    const int o0 = (t >> 4) * 4;
    float acc[4][4] = {};
#pragma unroll
    for (int j = 0; j < 12; j++) {
        float a[4], wv[4];
#pragma unroll
        for (int i = 0; i < 4; i++) {
            a[i]  = patch[(b0 + i) * 13 + j];
            wv[i] = wts[(o0 + i) * 13 + j];
        }
#pragma unroll
        for (int io = 0; io < 4; io++)
#pragma unroll
            for (int ib = 0; ib < 4; ib++)
                acc[io][ib] = fmaf(wv[io], a[ib], acc[io][ib]);
    }
#pragma unroll
    for (int io = 0; io < 4; io++) {
        float4 v;
        v.x = fmaxf(acc[io][0], 0.0f);
        v.y = fmaxf(acc[io][1], 0.0f);
        v.z = fmaxf(acc[io][2], 0.0f);
        v.w = fmaxf(acc[io][3], 0.0f);
        float* dst = g_out1 + (size_t)(p * 64 + o0 + io) * BATCH + bbase + b0;
        *reinterpret_cast<float4*>(dst) = v;
    }
}

// ---------------------------------------------------------------------------
// Feature-major f32x2 GEMM — R1/R2 double-buffered structure, NF=4,
// with the A staging remapped to stride-16 scalar columns so the
// transposed STS is bank-conflict-free:
//   thread (tx = t&15, ka = t>>4) loads A[k=k0+ka][bbase + tx + i*16], i<8,
//   stores As[(tx + i*16)*PAD + ka]  -> banks (18*tx + ka) % 32: all distinct.
// Compute loop identical to R2 (8x4 f32x2 accumulators, K packed in lanes).
// ---------------------------------------------------------------------------
template <int ABUF, int CBUF, bool GATHER, bool RELU>
__global__ __launch_bounds__(256, 2) void gemm_kernel(
    const float* __restrict__ W, int Kdim)
{
    constexpr int BM = 128, BN = 64, BK = 16, PAD = 18;
    __shared__ __align__(16) float As[2][BM * PAD];  // [b_local][k]
    __shared__ __align__(16) float Ws[2][BN * PAD];  // [o_local][k]

    const float* A = (ABUF == 0) ? g_out1 : (ABUF == 1) ? g_out2
                   : (ABUF == 2) ? g_h1   : g_h2;
    float* C       = (CBUF == 1) ? g_out2 : (CBUF == 2) ? g_h1 : g_h2;

    const int t     = threadIdx.x;
    const int bbase = blockIdx.x * BM;
    const int obase = blockIdx.y * BN;
    const int p2    = GATHER ? (int)blockIdx.z : 0;
    const int h2    = p2 / 7;
    const int w2    = p2 % 7;

    const int tx = t & 15;           // batch lane (also epilogue sub-index)
    const int ty = t >> 4;           // k row for A-load / feature sub-index
    const int owr = t >> 2;          // W tile row (o offset 0..63)
    const int kw4 = (t & 3) * 4;     // W tile col (k offset)

    float ra[8];
    float4 rw;

    auto load_regs = [&](int k0) {
        const int k = k0 + ty;
        const float* arow;
        if (GATHER) {
            int c = k >> 4, kh = (k >> 2) & 3, kw = k & 3;
            int pix = (2 * h2 + kh) * 16 + (2 * w2 + kw);
            arow = A + (size_t)(pix * 64 + c) * BATCH;
        } else {
            arow = A + (size_t)k * BATCH;
        }
        const float* ap = arow + bbase + tx;
#pragma unroll
        for (int i = 0; i < 8; i++) ra[i] = ap[i * 16];
        const float* wrow;
        if (GATHER) wrow = W + ((size_t)(obase + owr) * 49 + p2) * 1024 + k0 + kw4;
        else        wrow = W + (size_t)(obase + owr) * Kdim + k0 + kw4;
        rw = *reinterpret_cast<const float4*>(wrow);
    };

    auto store_smem = [&](int buf) {
        float* as = As[buf];
        float* ws = Ws[buf];
#pragma unroll
        for (int i = 0; i < 8; i++)
            as[(tx + i * 16) * PAD + ty] = ra[i];   // conflict-free scatter
        ws[owr * PAD + kw4 + 0] = rw.x;
        ws[owr * PAD + kw4 + 1] = rw.y;
        ws[owr * PAD + kw4 + 2] = rw.z;
        ws[owr * PAD + kw4 + 3] = rw.w;
    };

    unsigned long long acc[8][4];
#pragma unroll
    for (int i = 0; i < 8; i++)
#pragma unroll
        for (int j = 0; j < 4; j++) acc[i][j] = 0ull;

    // Prologue: first tile into buffer 0
    load_regs(0);
    store_smem(0);

    int cur = 0;
    for (int k0 = 0; k0 < Kdim; k0 += BK) {
        __syncthreads();
        const bool has_next = (k0 + BK) < Kdim;
        if (has_next) load_regs(k0 + BK);   // LDG in flight over compute

        const float* as = As[cur];
        const float* ws = Ws[cur];
#pragma unroll
        for (int kk = 0; kk < BK; kk += 2) {
            unsigned long long a2[8], w2r[4];
#pragma unroll
            for (int i = 0; i < 8; i++)
                a2[i] = *reinterpret_cast<const unsigned long long*>(
                    &as[(tx + i * 16) * PAD + kk]);
#pragma unroll
            for (int j = 0; j < 4; j++)
                w2r[j] = *reinterpret_cast<const unsigned long long*>(
                    &ws[(ty + j * 16) * PAD + kk]);
#pragma unroll
            for (int i = 0; i < 8; i++)
#pragma unroll
                for (int j = 0; j < 4; j++)
                    FMA_F32X2(acc[i][j], a2[i], w2r[j]);
        }

        if (has_next) store_smem(cur ^ 1);  // other buffer; next sync protects
        cur ^= 1;
    }

    // Epilogue: fold the two K-lanes, activation, feature-major store
#pragma unroll
    for (int j = 0; j < 4; j++) {
        const int o = obase + ty + j * 16;
        const size_t crow = GATHER ? (size_t)(o * 49 + p2) : (size_t)o;
        float* cb = C + crow * BATCH + bbase + tx;
#pragma unroll
        for (int i = 0; i < 8; i++) {
            unsigned long long v = acc[i][j];
            float lo = __uint_as_float((unsigned)(v & 0xffffffffu));
            float hi = __uint_as_float((unsigned)(v >> 32));
            float r = lo + hi;
            if (RELU) r = fmaxf(r, 0.0f);
            cb[i * 16] = r;
        }
    }
}

// ---------------------------------------------------------------------------
// FC3 (verbatim from R2-passing kernel)
// ---------------------------------------------------------------------------
__global__ __launch_bounds__(256) void fc3_kernel(
    const float* __restrict__ W, float* __restrict__ out)
{
    __shared__ float Ws[10 * 512];
    for (int i = threadIdx.x; i < 5120; i += 256) Ws[i] = W[i];
    __syncthreads();

    const int b = blockIdx.x * 256 + threadIdx.x;
    float acc[10] = {};
    for (int k = 0; k < 512; k++) {
        float a = g_h2[(size_t)k * BATCH + b];
#pragma unroll
        for (int o = 0; o < 10; o++)
            acc[o] = fmaf(a, Ws[o * 512 + k], acc[o]);
    }
#pragma unroll
    for (int o = 0; o < 10; o++) out[(size_t)b * 10 + o] = acc[o];
}

// ---------------------------------------------------------------------------
// kernel_launch (same 5-launch structure as R2)
// ---------------------------------------------------------------------------
extern "C" void kernel_launch(void* const* d_in, const int* in_sizes, int n_in,
                              void* d_out, int out_size)
{
    (void)in_sizes; (void)n_in; (void)out_size;
    const float* x      = (const float*)d_in[0];
    const float* conv1w = (const float*)d_in[1];
    const float* conv2w = (const float*)d_in[2];
    const float* fc1    = (const float*)d_in[3];
    const float* fc2    = (const float*)d_in[4];
    const float* fc3    = (const float*)d_in[5];
    float* out          = (float*)d_out;

    // Layer 1: 256 positions x 64 batch tiles
    layer1_kernel<<<dim3(256, 64), 256>>>(x, conv1w);

    // Layer 2: 49 x (M=4096, N=64, K=1024) locally-connected GEMMs
    gemm_kernel<0, 1, true, true><<<dim3(32, 1, 49), 256>>>(conv2w, 1024);

    // FC1: M=4096, N=1024, K=3136
    gemm_kernel<1, 2, false, true><<<dim3(32, 16), 256>>>(fc1, 3136);

    // FC2: M=4096, N=512, K=1024
    gemm_kernel<2, 3, false, true><<<dim3(32, 8), 256>>>(fc2, 1024);

    // FC3: M=4096, N=10, K=512
    fc3_kernel<<<16, 256>>>(fc3, out);
}